// round 8
// baseline (speedup 1.0000x reference)
#include <cuda_runtime.h>
#include <cuda_bf16.h>
#include <cstdint>

#define H_    56
#define W_    56
#define NH_   12
#define HD    64
#define NTOK  3137          // 56*56 + 1
#define C_    768
#define C3    2304
#define B_    8
#define MTOT  (B_ * NTOK)   // 25096
#define KDIM  768
#define BK    32
#define NSTG  (KDIM / BK)   // 24

// ---------------- scratch (__device__ globals; no cudaMalloc allowed) -------
__device__ float         g_qkv[(size_t)MTOT * C3];   // fp32 QKV activations
__device__ float         g_att[(size_t)MTOT * C_];   // fp32 row-partial / unused tok0
__device__ float         g_sc [(size_t)B_ * NH_ * H_ * W_ * 64]; // col scores/probs
__device__ __nv_bfloat16 g_xh [(size_t)MTOT * C_];   // x split hi/lo
__device__ __nv_bfloat16 g_xl [(size_t)MTOT * C_];
__device__ __nv_bfloat16 g_ath[(size_t)MTOT * C_];   // attention out hi/lo
__device__ __nv_bfloat16 g_atl[(size_t)MTOT * C_];
__device__ __nv_bfloat16 g_wqh[(size_t)C3 * C_];     // W_qkv^T split  [N,K]
__device__ __nv_bfloat16 g_wql[(size_t)C3 * C_];
__device__ __nv_bfloat16 g_wph[(size_t)C_ * C_];     // W_proj^T split [N,K]
__device__ __nv_bfloat16 g_wpl[(size_t)C_ * C_];

__device__ __forceinline__ void split2(float v, __nv_bfloat16& h, __nv_bfloat16& l) {
    h = __float2bfloat16(v);
    l = __float2bfloat16(v - __bfloat162float(h));
}
__device__ __forceinline__ uint32_t su32(const void* p) {
    uint32_t a;
    asm("{ .reg .u64 t; cvta.to.shared.u64 t, %1; cvt.u32.u64 %0, t; }"
        : "=r"(a) : "l"(p));
    return a;
}
__device__ __forceinline__ void cp16(uint32_t dst, const void* src, bool ok) {
    int sz = ok ? 16 : 0;
    asm volatile("cp.async.cg.shared.global [%0], [%1], 16, %2;"
                 :: "r"(dst), "l"(src), "r"(sz) : "memory");
}
__device__ __forceinline__ void mma16816(float* c, const uint32_t* a, const uint32_t* b) {
    asm volatile(
        "mma.sync.aligned.m16n8k16.row.col.f32.bf16.bf16.f32 "
        "{%0,%1,%2,%3}, {%4,%5,%6,%7}, {%8,%9}, {%0,%1,%2,%3};"
        : "+f"(c[0]), "+f"(c[1]), "+f"(c[2]), "+f"(c[3])
        : "r"(a[0]), "r"(a[1]), "r"(a[2]), "r"(a[3]), "r"(b[0]), "r"(b[1]));
}

// ---------------- pre-pass: fp32 -> bf16 hi/lo ------------------------------
__global__ __launch_bounds__(256) void k_split(
    const float* __restrict__ in, __nv_bfloat16* __restrict__ hi,
    __nv_bfloat16* __restrict__ lo, int n4)
{
    int i = blockIdx.x * 256 + threadIdx.x;
    if (i >= n4) return;
    float4 v = ((const float4*)in)[i];
    __nv_bfloat16 hv[4], lv[4];
    split2(v.x, hv[0], lv[0]);
    split2(v.y, hv[1], lv[1]);
    split2(v.z, hv[2], lv[2]);
    split2(v.w, hv[3], lv[3]);
    ((uint2*)hi)[i] = *(uint2*)hv;
    ((uint2*)lo)[i] = *(uint2*)lv;
}

// ---------------- pre-pass: transpose + split weights [R,Cn] -> [Cn,R] ------
__global__ __launch_bounds__(256) void k_tsplit(
    const float* __restrict__ W, __nv_bfloat16* __restrict__ th,
    __nv_bfloat16* __restrict__ tl, int R, int Cn)
{
    __shared__ float t[32][33];
    int x = blockIdx.x * 32 + threadIdx.x;
    int y = blockIdx.y * 32 + threadIdx.y;
#pragma unroll
    for (int j = 0; j < 32; j += 8)
        t[threadIdx.y + j][threadIdx.x] = W[(size_t)(y + j) * Cn + x];
    __syncthreads();
    int ox = blockIdx.y * 32 + threadIdx.x;
    int oy = blockIdx.x * 32 + threadIdx.y;
#pragma unroll
    for (int j = 0; j < 32; j += 8) {
        float v = t[threadIdx.x][threadIdx.y + j];
        __nv_bfloat16 h, l;
        split2(v, h, l);
        th[(size_t)(oy + j) * R + ox] = h;
        tl[(size_t)(oy + j) * R + ox] = l;
    }
}

// ---------------- bf16x3 GEMM via mma.sync (unchanged from R4) --------------
#define RS      20
#define TS      10240
#define STGB    (4 * TS)
#define GEMM_SMEM (2 * STGB)

__global__ __launch_bounds__(256) void gemm_mma(
    const __nv_bfloat16* __restrict__ Ah, const __nv_bfloat16* __restrict__ Al,
    const __nv_bfloat16* __restrict__ Bh, const __nv_bfloat16* __restrict__ Bl,
    float* __restrict__ Cc, const float* __restrict__ bias, int M, int N)
{
    extern __shared__ __align__(128) char smem[];
    const uint32_t sb = su32(smem);
    const int tid  = threadIdx.x;
    const int wid  = tid >> 5, lane = tid & 31;
    const int gid  = lane >> 2, tig = lane & 3;
    const int wm   = wid & 1, wn = wid >> 1;
    const int row0 = blockIdx.y * 128, col0 = blockIdx.x * 128;

    float acc[4][4][4];
#pragma unroll
    for (int i = 0; i < 4; ++i)
#pragma unroll
        for (int j = 0; j < 4; ++j)
#pragma unroll
            for (int k = 0; k < 4; ++k) acc[i][j][k] = 0.f;

    const int r0c = tid >> 2, j0c = tid & 3;
    const int r1c = (tid + 256) >> 2, j1c = tid & 3;

    auto issue = [&](int c) {
        const int k0 = c * BK;
        const uint32_t stg = sb + (c & 1) * STGB;
#pragma unroll
        for (int rep = 0; rep < 2; ++rep) {
            const int row = rep ? r1c : r0c;
            const int j   = rep ? j1c : j0c;
            const uint32_t d = stg + row * 80 + j * 16;
            const int grA = row0 + row;
            const bool okA = grA < M;
            const size_t aoff = (size_t)(okA ? grA : 0) * KDIM + k0 + j * 8;
            cp16(d,          Ah + aoff, okA);
            cp16(d + TS,     Al + aoff, okA);
            const size_t boff = (size_t)(col0 + row) * KDIM + k0 + j * 8;
            cp16(d + 2 * TS, Bh + boff, true);
            cp16(d + 3 * TS, Bl + boff, true);
        }
        asm volatile("cp.async.commit_group;" ::: "memory");
    };

    issue(0);

    for (int c = 0; c < NSTG; ++c) {
        if (c + 1 < NSTG) {
            issue(c + 1);
            asm volatile("cp.async.wait_group 1;" ::: "memory");
        } else {
            asm volatile("cp.async.wait_group 0;" ::: "memory");
        }
        __syncthreads();

        const uint32_t* sAh = (const uint32_t*)(smem + (c & 1) * STGB);
        const uint32_t* sAl = sAh + TS / 4;
        const uint32_t* sBh = sAh + 2 * TS / 4;
        const uint32_t* sBl = sAh + 3 * TS / 4;

#pragma unroll
        for (int kk = 0; kk < 2; ++kk) {
            const int h0 = kk * 8 + tig;
            uint32_t a[4][4], bh[4][2], bl[4][2];
#pragma unroll
            for (int mt = 0; mt < 4; ++mt) {
                const int rA = wm * 64 + mt * 16 + gid;
                a[mt][0] = sAh[rA * RS + h0];
                a[mt][1] = sAh[(rA + 8) * RS + h0];
                a[mt][2] = sAh[rA * RS + h0 + 4];
                a[mt][3] = sAh[(rA + 8) * RS + h0 + 4];
            }
#pragma unroll
            for (int nt = 0; nt < 4; ++nt) {
                const int n = wn * 32 + nt * 8 + gid;
                bh[nt][0] = sBh[n * RS + h0];
                bh[nt][1] = sBh[n * RS + h0 + 4];
                bl[nt][0] = sBl[n * RS + h0];
                bl[nt][1] = sBl[n * RS + h0 + 4];
            }
#pragma unroll
            for (int mt = 0; mt < 4; ++mt)
#pragma unroll
                for (int nt = 0; nt < 4; ++nt) mma16816(acc[mt][nt], a[mt], bh[nt]);
#pragma unroll
            for (int mt = 0; mt < 4; ++mt)
#pragma unroll
                for (int nt = 0; nt < 4; ++nt) mma16816(acc[mt][nt], a[mt], bl[nt]);
#pragma unroll
            for (int mt = 0; mt < 4; ++mt) {
                const int rA = wm * 64 + mt * 16 + gid;
                a[mt][0] = sAl[rA * RS + h0];
                a[mt][1] = sAl[(rA + 8) * RS + h0];
                a[mt][2] = sAl[rA * RS + h0 + 4];
                a[mt][3] = sAl[(rA + 8) * RS + h0 + 4];
            }
#pragma unroll
            for (int mt = 0; mt < 4; ++mt)
#pragma unroll
                for (int nt = 0; nt < 4; ++nt) mma16816(acc[mt][nt], a[mt], bh[nt]);
        }
        __syncthreads();
    }

#pragma unroll
    for (int mt = 0; mt < 4; ++mt) {
        const int gr = row0 + wm * 64 + mt * 16 + gid;
#pragma unroll
        for (int nt = 0; nt < 4; ++nt) {
            const int gc = col0 + wn * 32 + nt * 8 + tig * 2;
            float b0 = 0.f, b1 = 0.f;
            if (bias) { b0 = __ldg(bias + gc); b1 = __ldg(bias + gc + 1); }
            if (gr < M) {
                float2 v0 = make_float2(acc[mt][nt][0] + b0, acc[mt][nt][1] + b1);
                *(float2*)(Cc + (size_t)gr * N + gc) = v0;
            }
            if (gr + 8 < M) {
                float2 v1 = make_float2(acc[mt][nt][2] + b0, acc[mt][nt][3] + b1);
                *(float2*)(Cc + (size_t)(gr + 8) * N + gc) = v1;
            }
        }
    }
}

// ============================================================================
// Attention phase 1: column scores. Block=(w, head, b), 128 threads.
// S[h_q][j] = q(h_q,w) . k_col(j),  j=0 cls, j=1+h_k. Writes scaled scores.
// ============================================================================
#define QROWS 64
#define SST   68   // smem row stride (floats) for 64-dim tiles

__global__ __launch_bounds__(128) void k_colscore(
    const float* __restrict__ qkv, float* __restrict__ sc)
{
    __shared__ float Qs[QROWS * SST];     // queries (rows 56..63 zero)
    __shared__ float Ks[QROWS * SST];     // keys    (rows 57..63 zero)
    const int w = blockIdx.x, head = blockIdx.y, b = blockIdx.z;
    const int tid = threadIdx.x;
    const float* base = qkv + (size_t)b * NTOK * C3;
    const int qoff = head * HD;

    for (int idx = tid; idx < QROWS * 16; idx += 128) {
        const int r = idx >> 4, c = idx & 15;
        float4 v = make_float4(0.f, 0.f, 0.f, 0.f);
        if (r < 56) {
            const int n = 1 + r * W_ + w;
            v = *(const float4*)(base + (size_t)n * C3 + qoff + c * 4);
        }
        *(float4*)&Qs[r * SST + c * 4] = v;
    }
    for (int idx = tid; idx < QROWS * 16; idx += 128) {
        const int r = idx >> 4, c = idx & 15;
        float4 v = make_float4(0.f, 0.f, 0.f, 0.f);
        if (r < 57) {
            const int n = (r == 0) ? 0 : (1 + (r - 1) * W_ + w);
            v = *(const float4*)(base + (size_t)n * C3 + C_ + qoff + c * 4);
        }
        *(float4*)&Ks[r * SST + c * 4] = v;
    }
    __syncthreads();

    const int ty = tid >> 3, tx = tid & 7;
    float acc[4][8];
#pragma unroll
    for (int i = 0; i < 4; ++i)
#pragma unroll
        for (int j = 0; j < 8; ++j) acc[i][j] = 0.f;

#pragma unroll 4
    for (int d = 0; d < HD; d += 4) {
        float4 a4[4], b4[8];
#pragma unroll
        for (int i = 0; i < 4; ++i) a4[i] = *(float4*)&Qs[(ty + 16 * i) * SST + d];
#pragma unroll
        for (int j = 0; j < 8; ++j) b4[j] = *(float4*)&Ks[(tx + 8 * j) * SST + d];
#pragma unroll
        for (int i = 0; i < 4; ++i)
#pragma unroll
            for (int j = 0; j < 8; ++j) {
                acc[i][j] += a4[i].x * b4[j].x;
                acc[i][j] += a4[i].y * b4[j].y;
                acc[i][j] += a4[i].z * b4[j].z;
                acc[i][j] += a4[i].w * b4[j].w;
            }
    }

    float* out = sc + ((((size_t)b * NH_ + head) * H_) * W_ + w) * 64;
#pragma unroll
    for (int i = 0; i < 4; ++i) {
        const int hq = ty + 16 * i;
        if (hq >= 56) continue;
#pragma unroll
        for (int j = 0; j < 8; ++j) {
            const int jk = tx + 8 * j;
            if (jk < 57)
                out[(size_t)hq * (W_ * 64) + jk] = acc[i][j] * 0.125f;
        }
    }
}

// ============================================================================
// Attention phase 2: row scores + full softmax + row aggregation.
// Block=(h, head, b), 128 threads, dynamic smem.
//   P[64][132]: cols [0,57) = col scores/probs, cols [60,124) = row scores.
// Writes row partial to g_att (fp32), normalized col probs back to sc.
// ============================================================================
#define PST 132
#define K2_SMEM ((2 * QROWS * SST + QROWS * PST) * 4)   // Qs/Vr + Kr + P

__global__ __launch_bounds__(128) void k_rowfused(
    const float* __restrict__ qkv, float* __restrict__ sc,
    float* __restrict__ attp)
{
    extern __shared__ float sm[];
    float* Qs = sm;                       // later reused as Vr
    float* Kr = sm + QROWS * SST;
    float* P  = sm + 2 * QROWS * SST;
    const int h = blockIdx.x, head = blockIdx.y, b = blockIdx.z;
    const int tid = threadIdx.x;
    const float* base = qkv + (size_t)b * NTOK * C3;
    const int qoff = head * HD;
    const int nrow0 = 1 + h * W_;

    for (int idx = tid; idx < QROWS * 16; idx += 128) {
        const int r = idx >> 4, c = idx & 15;
        float4 qv = make_float4(0.f, 0.f, 0.f, 0.f);
        float4 kv = qv;
        if (r < 56) {
            const float* tok = base + (size_t)(nrow0 + r) * C3;
            qv = *(const float4*)(tok + qoff + c * 4);
            kv = *(const float4*)(tok + C_ + qoff + c * 4);
        }
        *(float4*)&Qs[r * SST + c * 4] = qv;
        *(float4*)&Kr[r * SST + c * 4] = kv;
    }
    __syncthreads();

    const int ty = tid >> 3, tx = tid & 7;
    {
        float acc[4][8];
#pragma unroll
        for (int i = 0; i < 4; ++i)
#pragma unroll
            for (int j = 0; j < 8; ++j) acc[i][j] = 0.f;
#pragma unroll 4
        for (int d = 0; d < HD; d += 4) {
            float4 a4[4], b4[8];
#pragma unroll
            for (int i = 0; i < 4; ++i) a4[i] = *(float4*)&Qs[(ty + 16 * i) * SST + d];
#pragma unroll
            for (int j = 0; j < 8; ++j) b4[j] = *(float4*)&Kr[(tx + 8 * j) * SST + d];
#pragma unroll
            for (int i = 0; i < 4; ++i)
#pragma unroll
                for (int j = 0; j < 8; ++j) {
                    acc[i][j] += a4[i].x * b4[j].x;
                    acc[i][j] += a4[i].y * b4[j].y;
                    acc[i][j] += a4[i].z * b4[j].z;
                    acc[i][j] += a4[i].w * b4[j].w;
                }
        }
#pragma unroll
        for (int i = 0; i < 4; ++i) {
            const int q = ty + 16 * i;
#pragma unroll
            for (int j = 0; j < 8; ++j) {
                const int k = tx + 8 * j;
                P[q * PST + 60 + k] = (k == q) ? -1e30f : acc[i][j] * 0.125f;
            }
        }
    }
    __syncthreads();

    // reload Vr into Qs space; pull col scores into P[:, 0..56]
    for (int idx = tid; idx < 56 * 16; idx += 128) {
        const int r = idx >> 4, c = idx & 15;
        *(float4*)&Qs[r * SST + c * 4] =
            *(const float4*)(base + (size_t)(nrow0 + r) * C3 + 2 * C_ + qoff + c * 4);
    }
    {
        const float* scb = sc + ((((size_t)b * NH_ + head) * H_ + h) * W_) * 64;
        for (int idx = tid; idx < 56 * 57; idx += 128) {
            const int q = idx / 57, j = idx % 57;
            P[q * PST + j] = scb[(size_t)q * 64 + j];
        }
    }
    __syncthreads();

    // softmax over 113 entries per query (cols 0..56 and 60..115)
    if (tid < 56) {
        float* row = P + tid * PST;
        float m = -1e30f;
#pragma unroll 4
        for (int j = 0; j < 57; ++j) m = fmaxf(m, row[j]);
#pragma unroll 4
        for (int j = 60; j < 116; ++j) m = fmaxf(m, row[j]);
        float s = 0.f;
#pragma unroll 4
        for (int j = 0; j < 57; ++j) { float e = __expf(row[j] - m); row[j] = e; s += e; }
#pragma unroll 4
        for (int j = 60; j < 116; ++j) { float e = __expf(row[j] - m); row[j] = e; s += e; }
        const float inv = 1.f / s;
#pragma unroll 4
        for (int j = 0; j < 57; ++j) row[j] *= inv;
#pragma unroll 4
        for (int j = 60; j < 116; ++j) row[j] *= inv;
    }
    __syncthreads();

    // write normalized col probs back to scratch
    {
        float* scb = sc + ((((size_t)b * NH_ + head) * H_ + h) * W_) * 64;
        for (int idx = tid; idx < 56 * 57; idx += 128) {
            const int q = idx / 57, j = idx % 57;
            scb[(size_t)q * 64 + j] = P[q * PST + j];
        }
    }

    // row aggregation: out[q][d] = sum_k P[q][60+k] * Vr[k][d]
    {
        float acc[4][8];
#pragma unroll
        for (int i = 0; i < 4; ++i)
#pragma unroll
            for (int j = 0; j < 8; ++j) acc[i][j] = 0.f;
        for (int k = 0; k < 56; ++k) {
            float af[4], bf[8];
#pragma unroll
            for (int i = 0; i < 4; ++i) af[i] = P[(ty + 16 * i) * PST + 60 + k];
#pragma unroll
            for (int j = 0; j < 8; ++j) bf[j] = Qs[k * SST + tx + 8 * j];
#pragma unroll
            for (int i = 0; i < 4; ++i)
#pragma unroll
                for (int j = 0; j < 8; ++j) acc[i][j] += af[i] * bf[j];
        }
#pragma unroll
        for (int i = 0; i < 4; ++i) {
            const int q = ty + 16 * i;
            if (q >= 56) continue;
            float* op = attp + ((size_t)b * NTOK + nrow0 + q) * C_ + qoff;
#pragma unroll
            for (int j = 0; j < 8; ++j) op[tx + 8 * j] = acc[i][j];
        }
    }
}

// ============================================================================
// Attention phase 3: column aggregation + final hi/lo emit.
// Block=(w, head, b), 128 threads.
// ============================================================================
__global__ __launch_bounds__(128) void k_colagg(
    const float* __restrict__ qkv, const float* __restrict__ sc,
    const float* __restrict__ attp,
    __nv_bfloat16* __restrict__ outh, __nv_bfloat16* __restrict__ outl)
{
    __shared__ float Vc[57 * SST];
    __shared__ float Pc[64 * 60];
    const int w = blockIdx.x, head = blockIdx.y, b = blockIdx.z;
    const int tid = threadIdx.x;
    const float* base = qkv + (size_t)b * NTOK * C3;
    const int qoff = head * HD;

    for (int idx = tid; idx < 57 * 16; idx += 128) {
        const int r = idx >> 4, c = idx & 15;
        const int n = (r == 0) ? 0 : (1 + (r - 1) * W_ + w);
        *(float4*)&Vc[r * SST + c * 4] =
            *(const float4*)(base + (size_t)n * C3 + 2 * C_ + qoff + c * 4);
    }
    {
        const float* scb = sc + (((size_t)b * NH_ + head) * H_) * (W_ * 64) + (size_t)w * 64;
        for (int idx = tid; idx < 56 * 57; idx += 128) {
            const int q = idx / 57, j = idx % 57;   // q = h of query
            Pc[q * 60 + j] = scb[(size_t)q * (W_ * 64) + j];
        }
    }
    __syncthreads();

    const int ty = tid >> 3, tx = tid & 7;
    float acc[4][8];
#pragma unroll
    for (int i = 0; i < 4; ++i)
#pragma unroll
        for (int j = 0; j < 8; ++j) acc[i][j] = 0.f;
    for (int k = 0; k < 57; ++k) {
        float af[4], bf[8];
#pragma unroll
        for (int i = 0; i < 4; ++i) af[i] = Pc[(ty + 16 * i) * 60 + k];
#pragma unroll
        for (int j = 0; j < 8; ++j) bf[j] = Vc[k * SST + tx + 8 * j];
#pragma unroll
        for (int i = 0; i < 4; ++i)
#pragma unroll
            for (int j = 0; j < 8; ++j) acc[i][j] += af[i] * bf[j];
    }
#pragma unroll
    for (int i = 0; i < 4; ++i) {
        const int hq = ty + 16 * i;
        if (hq >= 56) continue;
        const size_t off = ((size_t)b * NTOK + 1 + hq * W_ + w) * C_ + qoff;
#pragma unroll
        for (int j = 0; j < 8; ++j) {
            const int d = tx + 8 * j;
            float v = acc[i][j] + attp[off + d];
            __nv_bfloat16 hh, ll;
            split2(v, hh, ll);
            outh[off + d] = hh;
            outl[off + d] = ll;
        }
    }
}

// ---------------- CLS-token attention (unchanged) ---------------------------
__global__ __launch_bounds__(256) void attn_cls(
    const float* __restrict__ qkv,
    __nv_bfloat16* __restrict__ outh, __nv_bfloat16* __restrict__ outl)
{
    const int b  = blockIdx.x / NH_;
    const int nh = blockIdx.x % NH_;
    const int tid = threadIdx.x;

    __shared__ float qs[HD];
    __shared__ float scs[NTOK];
    __shared__ float red[256];
    __shared__ float part[4][HD];

    const float* base = qkv + (size_t)b * NTOK * C3;
    if (tid < HD) qs[tid] = base[nh * HD + tid];
    __syncthreads();

    for (int n = tid; n < NTOK; n += 256) {
        const float* kp = base + (size_t)n * C3 + C_ + nh * HD;
        float s = 0.f;
#pragma unroll
        for (int d = 0; d < HD; ++d) s += qs[d] * kp[d];
        scs[n] = s * 0.125f;
    }
    __syncthreads();

    float m = -1e30f;
    for (int n = tid; n < NTOK; n += 256) m = fmaxf(m, scs[n]);
    red[tid] = m;
    __syncthreads();
    for (int st = 128; st; st >>= 1) {
        if (tid < st) red[tid] = fmaxf(red[tid], red[tid + st]);
        __syncthreads();
    }
    m = red[0];
    __syncthreads();

    float s = 0.f;
    for (int n = tid; n < NTOK; n += 256) {
        float e = __expf(scs[n] - m);
        scs[n] = e;
        s += e;
    }
    red[tid] = s;
    __syncthreads();
    for (int st = 128; st; st >>= 1) {
        if (tid < st) red[tid] += red[tid + st];
        __syncthreads();
    }
    const float inv = 1.f / red[0];
    __syncthreads();

    const int d = tid & 63, chunk = tid >> 6;
    float acc = 0.f;
    for (int n = chunk; n < NTOK; n += 4) {
        const float* vp = base + (size_t)n * C3 + 2 * C_ + nh * HD;
        acc += scs[n] * vp[d];
    }
    part[chunk][d] = acc;
    __syncthreads();
    if (chunk == 0) {
        float r = (part[0][d] + part[1][d] + part[2][d] + part[3][d]) * inv;
        __nv_bfloat16 hh, ll;
        split2(r, hh, ll);
        const size_t ooff = (size_t)b * NTOK * C_ + nh * HD + d;
        outh[ooff] = hh;
        outl[ooff] = ll;
    }
}

// ---------------------------------------------------------------------------
extern "C" void kernel_launch(void* const* d_in, const int* in_sizes, int n_in,
                              void* d_out, int out_size)
{
    const float* x     = (const float*)d_in[0];
    const float* Wqkv  = (const float*)d_in[1];
    const float* Wproj = (const float*)d_in[2];
    const float* bproj = (const float*)d_in[3];
    float* out = (float*)d_out;

    float *qkv, *att, *sc;
    __nv_bfloat16 *xh, *xl, *ath, *atl, *wqh, *wql, *wph, *wpl;
    cudaGetSymbolAddress((void**)&qkv, g_qkv);
    cudaGetSymbolAddress((void**)&att, g_att);
    cudaGetSymbolAddress((void**)&sc,  g_sc);
    cudaGetSymbolAddress((void**)&xh,  g_xh);
    cudaGetSymbolAddress((void**)&xl,  g_xl);
    cudaGetSymbolAddress((void**)&ath, g_ath);
    cudaGetSymbolAddress((void**)&atl, g_atl);
    cudaGetSymbolAddress((void**)&wqh, g_wqh);
    cudaGetSymbolAddress((void**)&wql, g_wql);
    cudaGetSymbolAddress((void**)&wph, g_wph);
    cudaGetSymbolAddress((void**)&wpl, g_wpl);

    cudaFuncSetAttribute(gemm_mma,
                         cudaFuncAttributeMaxDynamicSharedMemorySize, GEMM_SMEM);
    cudaFuncSetAttribute(k_rowfused,
                         cudaFuncAttributeMaxDynamicSharedMemorySize, K2_SMEM);

    // 0) pre-passes
    {
        int n4 = MTOT * C_ / 4;
        k_split<<<(n4 + 255) / 256, 256>>>(x, xh, xl, n4);
        k_tsplit<<<dim3(C3 / 32, C_ / 32), dim3(32, 8)>>>(Wqkv,  wqh, wql, C_, C3);
        k_tsplit<<<dim3(C_ / 32, C_ / 32), dim3(32, 8)>>>(Wproj, wph, wpl, C_, C_);
    }
    // 1) QKV projection (HMMA bf16x3)
    gemm_mma<<<dim3(C3 / 128, (MTOT + 127) / 128), 256, GEMM_SMEM>>>(
        xh, xl, wqh, wql, qkv, nullptr, MTOT, C3);
    // 2) attention phases
    {
        dim3 ag(W_, NH_, B_);
        k_colscore<<<ag, 128>>>(qkv, sc);
        dim3 rg(H_, NH_, B_);
        k_rowfused<<<rg, 128, K2_SMEM>>>(qkv, sc, att);
        attn_cls<<<B_ * NH_, 256>>>(qkv, ath, atl);
        k_colagg<<<ag, 128>>>(qkv, sc, att, ath, atl);
    }
    // 3) output projection + bias (HMMA bf16x3)
    gemm_mma<<<dim3(C_ / 128, (MTOT + 127) / 128), 256, GEMM_SMEM>>>(
        ath, atl, wph, wpl, out, bproj, MTOT, C_);
}

// round 9
// speedup vs baseline: 1.0224x; 1.0224x over previous
#include <cuda_runtime.h>
#include <cuda_bf16.h>
#include <cstdint>

#define H_    56
#define W_    56
#define NH_   12
#define HD    64
#define NTOK  3137          // 56*56 + 1
#define C_    768
#define C3    2304
#define B_    8
#define MTOT  (B_ * NTOK)   // 25096
#define KDIM  768
#define BK    32
#define NSTG  (KDIM / BK)   // 24

// ---------------- scratch (__device__ globals; no cudaMalloc allowed) -------
__device__ float         g_qkv[(size_t)MTOT * C3];   // fp32 QKV activations
__device__ float         g_att[(size_t)MTOT * C_];   // fp32 row-partial
__device__ float         g_sc [(size_t)B_ * NH_ * H_ * W_ * 64]; // col scores/probs
__device__ __nv_bfloat16 g_xh [(size_t)MTOT * C_];   // x split hi/lo
__device__ __nv_bfloat16 g_xl [(size_t)MTOT * C_];
__device__ __nv_bfloat16 g_ath[(size_t)MTOT * C_];   // attention out hi/lo
__device__ __nv_bfloat16 g_atl[(size_t)MTOT * C_];
__device__ __nv_bfloat16 g_wqh[(size_t)C3 * C_];     // W_qkv^T split  [N,K]
__device__ __nv_bfloat16 g_wql[(size_t)C3 * C_];
__device__ __nv_bfloat16 g_wph[(size_t)C_ * C_];     // W_proj^T split [N,K]
__device__ __nv_bfloat16 g_wpl[(size_t)C_ * C_];

__device__ __forceinline__ void split2(float v, __nv_bfloat16& h, __nv_bfloat16& l) {
    h = __float2bfloat16(v);
    l = __float2bfloat16(v - __bfloat162float(h));
}
__device__ __forceinline__ uint32_t su32(const void* p) {
    uint32_t a;
    asm("{ .reg .u64 t; cvta.to.shared.u64 t, %1; cvt.u32.u64 %0, t; }"
        : "=r"(a) : "l"(p));
    return a;
}
__device__ __forceinline__ void cp16(uint32_t dst, const void* src, bool ok) {
    int sz = ok ? 16 : 0;
    asm volatile("cp.async.cg.shared.global [%0], [%1], 16, %2;"
                 :: "r"(dst), "l"(src), "r"(sz) : "memory");
}
__device__ __forceinline__ void mma16816(float* c, const uint32_t* a, const uint32_t* b) {
    asm volatile(
        "mma.sync.aligned.m16n8k16.row.col.f32.bf16.bf16.f32 "
        "{%0,%1,%2,%3}, {%4,%5,%6,%7}, {%8,%9}, {%0,%1,%2,%3};"
        : "+f"(c[0]), "+f"(c[1]), "+f"(c[2]), "+f"(c[3])
        : "r"(a[0]), "r"(a[1]), "r"(a[2]), "r"(a[3]), "r"(b[0]), "r"(b[1]));
}
__device__ __forceinline__ void ldsm4(uint32_t& r0, uint32_t& r1, uint32_t& r2,
                                      uint32_t& r3, uint32_t addr) {
    asm volatile("ldmatrix.sync.aligned.m8n8.x4.shared.b16 {%0,%1,%2,%3}, [%4];"
                 : "=r"(r0), "=r"(r1), "=r"(r2), "=r"(r3) : "r"(addr));
}

// ---------------- pre-pass: fp32 -> bf16 hi/lo ------------------------------
__global__ __launch_bounds__(256) void k_split(
    const float* __restrict__ in, __nv_bfloat16* __restrict__ hi,
    __nv_bfloat16* __restrict__ lo, int n4)
{
    int i = blockIdx.x * 256 + threadIdx.x;
    if (i >= n4) return;
    float4 v = ((const float4*)in)[i];
    __nv_bfloat16 hv[4], lv[4];
    split2(v.x, hv[0], lv[0]);
    split2(v.y, hv[1], lv[1]);
    split2(v.z, hv[2], lv[2]);
    split2(v.w, hv[3], lv[3]);
    ((uint2*)hi)[i] = *(uint2*)hv;
    ((uint2*)lo)[i] = *(uint2*)lv;
}

// ---------------- pre-pass: transpose + split weights [R,Cn] -> [Cn,R] ------
__global__ __launch_bounds__(256) void k_tsplit(
    const float* __restrict__ W, __nv_bfloat16* __restrict__ th,
    __nv_bfloat16* __restrict__ tl, int R, int Cn)
{
    __shared__ float t[32][33];
    int x = blockIdx.x * 32 + threadIdx.x;
    int y = blockIdx.y * 32 + threadIdx.y;
#pragma unroll
    for (int j = 0; j < 32; j += 8)
        t[threadIdx.y + j][threadIdx.x] = W[(size_t)(y + j) * Cn + x];
    __syncthreads();
    int ox = blockIdx.y * 32 + threadIdx.x;
    int oy = blockIdx.x * 32 + threadIdx.y;
#pragma unroll
    for (int j = 0; j < 32; j += 8) {
        float v = t[threadIdx.x][threadIdx.y + j];
        __nv_bfloat16 h, l;
        split2(v, h, l);
        th[(size_t)(oy + j) * R + ox] = h;
        tl[(size_t)(oy + j) * R + ox] = l;
    }
}

// ---------------- bf16x3 GEMM via mma.sync + ldmatrix -----------------------
#define RS      20          // row stride in uint32 (80 bytes)
#define TS      10240       // one tensor tile: 128 rows * 80 B
#define STGB    (4 * TS)    // Ah, Al, Bh, Bl
#define GEMM_SMEM (2 * STGB)

__global__ __launch_bounds__(256) void gemm_mma(
    const __nv_bfloat16* __restrict__ Ah, const __nv_bfloat16* __restrict__ Al,
    const __nv_bfloat16* __restrict__ Bh, const __nv_bfloat16* __restrict__ Bl,
    float* __restrict__ Cc, const float* __restrict__ bias, int M, int N)
{
    extern __shared__ __align__(128) char smem[];
    const uint32_t sb = su32(smem);
    const int tid  = threadIdx.x;
    const int wid  = tid >> 5, lane = tid & 31;
    const int gid  = lane >> 2, tig = lane & 3;
    const int wm   = wid & 1, wn = wid >> 1;          // 2 x 4 warp grid
    const int row0 = blockIdx.y * 128, col0 = blockIdx.x * 128;

    float acc[4][4][4];
#pragma unroll
    for (int i = 0; i < 4; ++i)
#pragma unroll
        for (int j = 0; j < 4; ++j)
#pragma unroll
            for (int k = 0; k < 4; ++k) acc[i][j][k] = 0.f;

    // per-lane ldmatrix base offsets (within a stage's tensor tile)
    // A: rows of m16 tile; kOff selects k-halves
    const uint32_t aLm = (uint32_t)((wm * 64 + (lane & 7) + ((lane >> 3) & 1) * 8) * 80
                                    + ((lane >> 4) & 1) * 16);
    // B: rows of two n8 tiles; kOff on bit3
    const uint32_t bLm = (uint32_t)((wn * 32 + (lane & 7) + ((lane >> 4) & 1) * 8) * 80
                                    + ((lane >> 3) & 1) * 16);

    // cp.async mapping: 512 16B-chunks per tensor; thread does chunk tid, tid+256
    const int r0c = tid >> 2, j0c = tid & 3;
    const int r1c = (tid + 256) >> 2, j1c = tid & 3;

    auto issue = [&](int c) {
        const int k0 = c * BK;
        const uint32_t stg = sb + (c & 1) * STGB;
#pragma unroll
        for (int rep = 0; rep < 2; ++rep) {
            const int row = rep ? r1c : r0c;
            const int j   = rep ? j1c : j0c;
            const uint32_t d = stg + row * 80 + j * 16;
            const int grA = row0 + row;
            const bool okA = grA < M;
            const size_t aoff = (size_t)(okA ? grA : 0) * KDIM + k0 + j * 8;
            cp16(d,          Ah + aoff, okA);
            cp16(d + TS,     Al + aoff, okA);
            const size_t boff = (size_t)(col0 + row) * KDIM + k0 + j * 8;
            cp16(d + 2 * TS, Bh + boff, true);
            cp16(d + 3 * TS, Bl + boff, true);
        }
        asm volatile("cp.async.commit_group;" ::: "memory");
    };

    issue(0);

    for (int c = 0; c < NSTG; ++c) {
        if (c + 1 < NSTG) {
            issue(c + 1);
            asm volatile("cp.async.wait_group 1;" ::: "memory");
        } else {
            asm volatile("cp.async.wait_group 0;" ::: "memory");
        }
        __syncthreads();

        const uint32_t stg = sb + (c & 1) * STGB;
        const uint32_t aBase = stg + aLm;
        const uint32_t bBase = stg + bLm;

#pragma unroll
        for (int kk = 0; kk < 2; ++kk) {
            const uint32_t kOfs = kk * 32;
            uint32_t ah[4][4], al[4][4], bh[4][2], bl[4][2];
#pragma unroll
            for (int mt = 0; mt < 4; ++mt) {
                ldsm4(ah[mt][0], ah[mt][1], ah[mt][2], ah[mt][3],
                      aBase + mt * (16 * 80) + kOfs);
                ldsm4(al[mt][0], al[mt][1], al[mt][2], al[mt][3],
                      aBase + TS + mt * (16 * 80) + kOfs);
            }
#pragma unroll
            for (int pr = 0; pr < 2; ++pr) {      // each covers n-tiles 2pr, 2pr+1
                ldsm4(bh[2 * pr][0], bh[2 * pr][1], bh[2 * pr + 1][0], bh[2 * pr + 1][1],
                      bBase + 2 * TS + pr * (16 * 80) + kOfs);
                ldsm4(bl[2 * pr][0], bl[2 * pr][1], bl[2 * pr + 1][0], bl[2 * pr + 1][1],
                      bBase + 3 * TS + pr * (16 * 80) + kOfs);
            }
#pragma unroll
            for (int mt = 0; mt < 4; ++mt)
#pragma unroll
                for (int nt = 0; nt < 4; ++nt) mma16816(acc[mt][nt], ah[mt], bh[nt]);
#pragma unroll
            for (int mt = 0; mt < 4; ++mt)
#pragma unroll
                for (int nt = 0; nt < 4; ++nt) mma16816(acc[mt][nt], ah[mt], bl[nt]);
#pragma unroll
            for (int mt = 0; mt < 4; ++mt)
#pragma unroll
                for (int nt = 0; nt < 4; ++nt) mma16816(acc[mt][nt], al[mt], bh[nt]);
        }
        __syncthreads();
    }

    // epilogue
#pragma unroll
    for (int mt = 0; mt < 4; ++mt) {
        const int gr = row0 + wm * 64 + mt * 16 + gid;
#pragma unroll
        for (int nt = 0; nt < 4; ++nt) {
            const int gc = col0 + wn * 32 + nt * 8 + tig * 2;
            float b0 = 0.f, b1 = 0.f;
            if (bias) { b0 = __ldg(bias + gc); b1 = __ldg(bias + gc + 1); }
            if (gr < M) {
                float2 v0 = make_float2(acc[mt][nt][0] + b0, acc[mt][nt][1] + b1);
                *(float2*)(Cc + (size_t)gr * N + gc) = v0;
            }
            if (gr + 8 < M) {
                float2 v1 = make_float2(acc[mt][nt][2] + b0, acc[mt][nt][3] + b1);
                *(float2*)(Cc + (size_t)(gr + 8) * N + gc) = v1;
            }
        }
    }
}

// ============================================================================
// Attention phase 1: column scores. Block=(w, head, b), 128 threads.
// ============================================================================
#define QROWS 64
#define SST   68

__global__ __launch_bounds__(128) void k_colscore(
    const float* __restrict__ qkv, float* __restrict__ sc)
{
    __shared__ float Qs[QROWS * SST];
    __shared__ float Ks[QROWS * SST];
    const int w = blockIdx.x, head = blockIdx.y, b = blockIdx.z;
    const int tid = threadIdx.x;
    const float* base = qkv + (size_t)b * NTOK * C3;
    const int qoff = head * HD;

    for (int idx = tid; idx < QROWS * 16; idx += 128) {
        const int r = idx >> 4, c = idx & 15;
        float4 v = make_float4(0.f, 0.f, 0.f, 0.f);
        if (r < 56) {
            const int n = 1 + r * W_ + w;
            v = *(const float4*)(base + (size_t)n * C3 + qoff + c * 4);
        }
        *(float4*)&Qs[r * SST + c * 4] = v;
    }
    for (int idx = tid; idx < QROWS * 16; idx += 128) {
        const int r = idx >> 4, c = idx & 15;
        float4 v = make_float4(0.f, 0.f, 0.f, 0.f);
        if (r < 57) {
            const int n = (r == 0) ? 0 : (1 + (r - 1) * W_ + w);
            v = *(const float4*)(base + (size_t)n * C3 + C_ + qoff + c * 4);
        }
        *(float4*)&Ks[r * SST + c * 4] = v;
    }
    __syncthreads();

    const int ty = tid >> 3, tx = tid & 7;
    float acc[4][8];
#pragma unroll
    for (int i = 0; i < 4; ++i)
#pragma unroll
        for (int j = 0; j < 8; ++j) acc[i][j] = 0.f;

#pragma unroll 4
    for (int d = 0; d < HD; d += 4) {
        float4 a4[4], b4[8];
#pragma unroll
        for (int i = 0; i < 4; ++i) a4[i] = *(float4*)&Qs[(ty + 16 * i) * SST + d];
#pragma unroll
        for (int j = 0; j < 8; ++j) b4[j] = *(float4*)&Ks[(tx + 8 * j) * SST + d];
#pragma unroll
        for (int i = 0; i < 4; ++i)
#pragma unroll
            for (int j = 0; j < 8; ++j) {
                acc[i][j] += a4[i].x * b4[j].x;
                acc[i][j] += a4[i].y * b4[j].y;
                acc[i][j] += a4[i].z * b4[j].z;
                acc[i][j] += a4[i].w * b4[j].w;
            }
    }

    float* out = sc + ((((size_t)b * NH_ + head) * H_) * W_ + w) * 64;
#pragma unroll
    for (int i = 0; i < 4; ++i) {
        const int hq = ty + 16 * i;
        if (hq >= 56) continue;
#pragma unroll
        for (int j = 0; j < 8; ++j) {
            const int jk = tx + 8 * j;
            if (jk < 57)
                out[(size_t)hq * (W_ * 64) + jk] = acc[i][j] * 0.125f;
        }
    }
}

// ============================================================================
// Attention phase 2: row scores + full softmax + row aggregation.
// ============================================================================
#define PST 132
#define K2_SMEM ((2 * QROWS * SST + QROWS * PST) * 4)

__global__ __launch_bounds__(128) void k_rowfused(
    const float* __restrict__ qkv, float* __restrict__ sc,
    float* __restrict__ attp)
{
    extern __shared__ float sm[];
    float* Qs = sm;
    float* Kr = sm + QROWS * SST;
    float* P  = sm + 2 * QROWS * SST;
    const int h = blockIdx.x, head = blockIdx.y, b = blockIdx.z;
    const int tid = threadIdx.x;
    const float* base = qkv + (size_t)b * NTOK * C3;
    const int qoff = head * HD;
    const int nrow0 = 1 + h * W_;

    for (int idx = tid; idx < QROWS * 16; idx += 128) {
        const int r = idx >> 4, c = idx & 15;
        float4 qv = make_float4(0.f, 0.f, 0.f, 0.f);
        float4 kv = qv;
        if (r < 56) {
            const float* tok = base + (size_t)(nrow0 + r) * C3;
            qv = *(const float4*)(tok + qoff + c * 4);
            kv = *(const float4*)(tok + C_ + qoff + c * 4);
        }
        *(float4*)&Qs[r * SST + c * 4] = qv;
        *(float4*)&Kr[r * SST + c * 4] = kv;
    }
    __syncthreads();

    const int ty = tid >> 3, tx = tid & 7;
    {
        float acc[4][8];
#pragma unroll
        for (int i = 0; i < 4; ++i)
#pragma unroll
            for (int j = 0; j < 8; ++j) acc[i][j] = 0.f;
#pragma unroll 4
        for (int d = 0; d < HD; d += 4) {
            float4 a4[4], b4[8];
#pragma unroll
            for (int i = 0; i < 4; ++i) a4[i] = *(float4*)&Qs[(ty + 16 * i) * SST + d];
#pragma unroll
            for (int j = 0; j < 8; ++j) b4[j] = *(float4*)&Kr[(tx + 8 * j) * SST + d];
#pragma unroll
            for (int i = 0; i < 4; ++i)
#pragma unroll
                for (int j = 0; j < 8; ++j) {
                    acc[i][j] += a4[i].x * b4[j].x;
                    acc[i][j] += a4[i].y * b4[j].y;
                    acc[i][j] += a4[i].z * b4[j].z;
                    acc[i][j] += a4[i].w * b4[j].w;
                }
        }
#pragma unroll
        for (int i = 0; i < 4; ++i) {
            const int q = ty + 16 * i;
#pragma unroll
            for (int j = 0; j < 8; ++j) {
                const int k = tx + 8 * j;
                P[q * PST + 60 + k] = (k == q) ? -1e30f : acc[i][j] * 0.125f;
            }
        }
    }
    __syncthreads();

    for (int idx = tid; idx < 56 * 16; idx += 128) {
        const int r = idx >> 4, c = idx & 15;
        *(float4*)&Qs[r * SST + c * 4] =
            *(const float4*)(base + (size_t)(nrow0 + r) * C3 + 2 * C_ + qoff + c * 4);
    }
    {
        const float* scb = sc + ((((size_t)b * NH_ + head) * H_ + h) * W_) * 64;
        for (int idx = tid; idx < 56 * 57; idx += 128) {
            const int q = idx / 57, j = idx % 57;
            P[q * PST + j] = scb[(size_t)q * 64 + j];
        }
    }
    __syncthreads();

    if (tid < 56) {
        float* row = P + tid * PST;
        float m = -1e30f;
#pragma unroll 4
        for (int j = 0; j < 57; ++j) m = fmaxf(m, row[j]);
#pragma unroll 4
        for (int j = 60; j < 116; ++j) m = fmaxf(m, row[j]);
        float s = 0.f;
#pragma unroll 4
        for (int j = 0; j < 57; ++j) { float e = __expf(row[j] - m); row[j] = e; s += e; }
#pragma unroll 4
        for (int j = 60; j < 116; ++j) { float e = __expf(row[j] - m); row[j] = e; s += e; }
        const float inv = 1.f / s;
#pragma unroll 4
        for (int j = 0; j < 57; ++j) row[j] *= inv;
#pragma unroll 4
        for (int j = 60; j < 116; ++j) row[j] *= inv;
    }
    __syncthreads();

    {
        float* scb = sc + ((((size_t)b * NH_ + head) * H_ + h) * W_) * 64;
        for (int idx = tid; idx < 56 * 57; idx += 128) {
            const int q = idx / 57, j = idx % 57;
            scb[(size_t)q * 64 + j] = P[q * PST + j];
        }
    }

    {
        float acc[4][8];
#pragma unroll
        for (int i = 0; i < 4; ++i)
#pragma unroll
            for (int j = 0; j < 8; ++j) acc[i][j] = 0.f;
        for (int k = 0; k < 56; ++k) {
            float af[4], bf[8];
#pragma unroll
            for (int i = 0; i < 4; ++i) af[i] = P[(ty + 16 * i) * PST + 60 + k];
#pragma unroll
            for (int j = 0; j < 8; ++j) bf[j] = Qs[k * SST + tx + 8 * j];
#pragma unroll
            for (int i = 0; i < 4; ++i)
#pragma unroll
                for (int j = 0; j < 8; ++j) acc[i][j] += af[i] * bf[j];
        }
#pragma unroll
        for (int i = 0; i < 4; ++i) {
            const int q = ty + 16 * i;
            if (q >= 56) continue;
            float* op = attp + ((size_t)b * NTOK + nrow0 + q) * C_ + qoff;
#pragma unroll
            for (int j = 0; j < 8; ++j) op[tx + 8 * j] = acc[i][j];
        }
    }
}

// ============================================================================
// Attention phase 3: column aggregation + final hi/lo emit.
// ============================================================================
__global__ __launch_bounds__(128) void k_colagg(
    const float* __restrict__ qkv, const float* __restrict__ sc,
    const float* __restrict__ attp,
    __nv_bfloat16* __restrict__ outh, __nv_bfloat16* __restrict__ outl)
{
    __shared__ float Vc[57 * SST];
    __shared__ float Pc[64 * 60];
    const int w = blockIdx.x, head = blockIdx.y, b = blockIdx.z;
    const int tid = threadIdx.x;
    const float* base = qkv + (size_t)b * NTOK * C3;
    const int qoff = head * HD;

    for (int idx = tid; idx < 57 * 16; idx += 128) {
        const int r = idx >> 4, c = idx & 15;
        const int n = (r == 0) ? 0 : (1 + (r - 1) * W_ + w);
        *(float4*)&Vc[r * SST + c * 4] =
            *(const float4*)(base + (size_t)n * C3 + 2 * C_ + qoff + c * 4);
    }
    {
        const float* scb = sc + (((size_t)b * NH_ + head) * H_) * (W_ * 64) + (size_t)w * 64;
        for (int idx = tid; idx < 56 * 57; idx += 128) {
            const int q = idx / 57, j = idx % 57;
            Pc[q * 60 + j] = scb[(size_t)q * (W_ * 64) + j];
        }
    }
    __syncthreads();

    const int ty = tid >> 3, tx = tid & 7;
    float acc[4][8];
#pragma unroll
    for (int i = 0; i < 4; ++i)
#pragma unroll
        for (int j = 0; j < 8; ++j) acc[i][j] = 0.f;
    for (int k = 0; k < 57; ++k) {
        float af[4], bf[8];
#pragma unroll
        for (int i = 0; i < 4; ++i) af[i] = Pc[(ty + 16 * i) * 60 + k];
#pragma unroll
        for (int j = 0; j < 8; ++j) bf[j] = Vc[k * SST + tx + 8 * j];
#pragma unroll
        for (int i = 0; i < 4; ++i)
#pragma unroll
            for (int j = 0; j < 8; ++j) acc[i][j] += af[i] * bf[j];
    }
#pragma unroll
    for (int i = 0; i < 4; ++i) {
        const int hq = ty + 16 * i;
        if (hq >= 56) continue;
        const size_t off = ((size_t)b * NTOK + 1 + hq * W_ + w) * C_ + qoff;
#pragma unroll
        for (int j = 0; j < 8; ++j) {
            const int d = tx + 8 * j;
            float v = acc[i][j] + attp[off + d];
            __nv_bfloat16 hh, ll;
            split2(v, hh, ll);
            outh[off + d] = hh;
            outl[off + d] = ll;
        }
    }
}

// ---------------- CLS-token attention ---------------------------------------
__global__ __launch_bounds__(256) void attn_cls(
    const float* __restrict__ qkv,
    __nv_bfloat16* __restrict__ outh, __nv_bfloat16* __restrict__ outl)
{
    const int b  = blockIdx.x / NH_;
    const int nh = blockIdx.x % NH_;
    const int tid = threadIdx.x;

    __shared__ float qs[HD];
    __shared__ float scs[NTOK];
    __shared__ float red[256];
    __shared__ float part[4][HD];

    const float* base = qkv + (size_t)b * NTOK * C3;
    if (tid < HD) qs[tid] = base[nh * HD + tid];
    __syncthreads();

    for (int n = tid; n < NTOK; n += 256) {
        const float* kp = base + (size_t)n * C3 + C_ + nh * HD;
        float s = 0.f;
#pragma unroll
        for (int d = 0; d < HD; ++d) s += qs[d] * kp[d];
        scs[n] = s * 0.125f;
    }
    __syncthreads();

    float m = -1e30f;
    for (int n = tid; n < NTOK; n += 256) m = fmaxf(m, scs[n]);
    red[tid] = m;
    __syncthreads();
    for (int st = 128; st; st >>= 1) {
        if (tid < st) red[tid] = fmaxf(red[tid], red[tid + st]);
        __syncthreads();
    }
    m = red[0];
    __syncthreads();

    float s = 0.f;
    for (int n = tid; n < NTOK; n += 256) {
        float e = __expf(scs[n] - m);
        scs[n] = e;
        s += e;
    }
    red[tid] = s;
    __syncthreads();
    for (int st = 128; st; st >>= 1) {
        if (tid < st) red[tid] += red[tid + st];
        __syncthreads();
    }
    const float inv = 1.f / red[0];
    __syncthreads();

    const int d = tid & 63, chunk = tid >> 6;
    float acc = 0.f;
    for (int n = chunk; n < NTOK; n += 4) {
        const float* vp = base + (size_t)n * C3 + 2 * C_ + nh * HD;
        acc += scs[n] * vp[d];
    }
    part[chunk][d] = acc;
    __syncthreads();
    if (chunk == 0) {
        float r = (part[0][d] + part[1][d] + part[2][d] + part[3][d]) * inv;
        __nv_bfloat16 hh, ll;
        split2(r, hh, ll);
        const size_t ooff = (size_t)b * NTOK * C_ + nh * HD + d;
        outh[ooff] = hh;
        outl[ooff] = ll;
    }
}

// ---------------------------------------------------------------------------
extern "C" void kernel_launch(void* const* d_in, const int* in_sizes, int n_in,
                              void* d_out, int out_size)
{
    const float* x     = (const float*)d_in[0];
    const float* Wqkv  = (const float*)d_in[1];
    const float* Wproj = (const float*)d_in[2];
    const float* bproj = (const float*)d_in[3];
    float* out = (float*)d_out;

    float *qkv, *att, *sc;
    __nv_bfloat16 *xh, *xl, *ath, *atl, *wqh, *wql, *wph, *wpl;
    cudaGetSymbolAddress((void**)&qkv, g_qkv);
    cudaGetSymbolAddress((void**)&att, g_att);
    cudaGetSymbolAddress((void**)&sc,  g_sc);
    cudaGetSymbolAddress((void**)&xh,  g_xh);
    cudaGetSymbolAddress((void**)&xl,  g_xl);
    cudaGetSymbolAddress((void**)&ath, g_ath);
    cudaGetSymbolAddress((void**)&atl, g_atl);
    cudaGetSymbolAddress((void**)&wqh, g_wqh);
    cudaGetSymbolAddress((void**)&wql, g_wql);
    cudaGetSymbolAddress((void**)&wph, g_wph);
    cudaGetSymbolAddress((void**)&wpl, g_wpl);

    cudaFuncSetAttribute(gemm_mma,
                         cudaFuncAttributeMaxDynamicSharedMemorySize, GEMM_SMEM);
    cudaFuncSetAttribute(k_rowfused,
                         cudaFuncAttributeMaxDynamicSharedMemorySize, K2_SMEM);

    // 0) pre-passes
    {
        int n4 = MTOT * C_ / 4;
        k_split<<<(n4 + 255) / 256, 256>>>(x, xh, xl, n4);
        k_tsplit<<<dim3(C3 / 32, C_ / 32), dim3(32, 8)>>>(Wqkv,  wqh, wql, C_, C3);
        k_tsplit<<<dim3(C_ / 32, C_ / 32), dim3(32, 8)>>>(Wproj, wph, wpl, C_, C_);
    }
    // 1) QKV projection (HMMA bf16x3 + ldmatrix)
    gemm_mma<<<dim3(C3 / 128, (MTOT + 127) / 128), 256, GEMM_SMEM>>>(
        xh, xl, wqh, wql, qkv, nullptr, MTOT, C3);
    // 2) attention phases
    {
        dim3 ag(W_, NH_, B_);
        k_colscore<<<ag, 128>>>(qkv, sc);
        dim3 rg(H_, NH_, B_);
        k_rowfused<<<rg, 128, K2_SMEM>>>(qkv, sc, att);
        attn_cls<<<B_ * NH_, 256>>>(qkv, ath, atl);
        k_colagg<<<ag, 128>>>(qkv, sc, att, ath, atl);
    }
    // 3) output projection + bias (HMMA bf16x3 + ldmatrix)
    gemm_mma<<<dim3(C_ / 128, (MTOT + 127) / 128), 256, GEMM_SMEM>>>(
        ath, atl, wph, wpl, out, bproj, MTOT, C_);
}

// round 10
// speedup vs baseline: 1.1185x; 1.0940x over previous
#include <cuda_runtime.h>
#include <cuda_bf16.h>
#include <cstdint>

#define H_    56
#define W_    56
#define NH_   12
#define HD    64
#define NTOK  3137          // 56*56 + 1
#define C_    768
#define C3    2304
#define B_    8
#define MTOT  (B_ * NTOK)   // 25096
#define KDIM  768
#define BK    32
#define NSTG  (KDIM / BK)   // 24

// ---------------- scratch (__device__ globals; no cudaMalloc allowed) -------
__device__ float         g_qkv[(size_t)MTOT * C3];   // fp32 QKV activations
__device__ float         g_att[(size_t)MTOT * C_];   // fp32 row-partial
__device__ float         g_sc [(size_t)B_ * NH_ * H_ * W_ * 64]; // col scores/probs
__device__ __nv_bfloat16 g_xh [(size_t)MTOT * C_];   // x split hi/lo
__device__ __nv_bfloat16 g_xl [(size_t)MTOT * C_];
__device__ __nv_bfloat16 g_ath[(size_t)MTOT * C_];   // attention out hi/lo
__device__ __nv_bfloat16 g_atl[(size_t)MTOT * C_];
__device__ __nv_bfloat16 g_wqh[(size_t)C3 * C_];     // W_qkv^T split  [N,K]
__device__ __nv_bfloat16 g_wql[(size_t)C3 * C_];
__device__ __nv_bfloat16 g_wph[(size_t)C_ * C_];     // W_proj^T split [N,K]
__device__ __nv_bfloat16 g_wpl[(size_t)C_ * C_];

__device__ __forceinline__ void split2(float v, __nv_bfloat16& h, __nv_bfloat16& l) {
    h = __float2bfloat16(v);
    l = __float2bfloat16(v - __bfloat162float(h));
}
__device__ __forceinline__ uint32_t su32(const void* p) {
    uint32_t a;
    asm("{ .reg .u64 t; cvta.to.shared.u64 t, %1; cvt.u32.u64 %0, t; }"
        : "=r"(a) : "l"(p));
    return a;
}
__device__ __forceinline__ void cp16(uint32_t dst, const void* src, bool ok) {
    int sz = ok ? 16 : 0;
    asm volatile("cp.async.cg.shared.global [%0], [%1], 16, %2;"
                 :: "r"(dst), "l"(src), "r"(sz) : "memory");
}
__device__ __forceinline__ void mma16816(float* c, const uint32_t* a, const uint32_t* b) {
    asm volatile(
        "mma.sync.aligned.m16n8k16.row.col.f32.bf16.bf16.f32 "
        "{%0,%1,%2,%3}, {%4,%5,%6,%7}, {%8,%9}, {%0,%1,%2,%3};"
        : "+f"(c[0]), "+f"(c[1]), "+f"(c[2]), "+f"(c[3])
        : "r"(a[0]), "r"(a[1]), "r"(a[2]), "r"(a[3]), "r"(b[0]), "r"(b[1]));
}
__device__ __forceinline__ void ldsm4(uint32_t& r0, uint32_t& r1, uint32_t& r2,
                                      uint32_t& r3, uint32_t addr) {
    asm volatile("ldmatrix.sync.aligned.m8n8.x4.shared.b16 {%0,%1,%2,%3}, [%4];"
                 : "=r"(r0), "=r"(r1), "=r"(r2), "=r"(r3) : "r"(addr));
}

// ---------------- pre-pass: fp32 -> bf16 hi/lo ------------------------------
__global__ __launch_bounds__(256) void k_split(
    const float* __restrict__ in, __nv_bfloat16* __restrict__ hi,
    __nv_bfloat16* __restrict__ lo, int n4)
{
    int i = blockIdx.x * 256 + threadIdx.x;
    if (i >= n4) return;
    float4 v = ((const float4*)in)[i];
    __nv_bfloat16 hv[4], lv[4];
    split2(v.x, hv[0], lv[0]);
    split2(v.y, hv[1], lv[1]);
    split2(v.z, hv[2], lv[2]);
    split2(v.w, hv[3], lv[3]);
    ((uint2*)hi)[i] = *(uint2*)hv;
    ((uint2*)lo)[i] = *(uint2*)lv;
}

// ---------------- pre-pass: transpose + split weights [R,Cn] -> [Cn,R] ------
__global__ __launch_bounds__(256) void k_tsplit(
    const float* __restrict__ W, __nv_bfloat16* __restrict__ th,
    __nv_bfloat16* __restrict__ tl, int R, int Cn)
{
    __shared__ float t[32][33];
    int x = blockIdx.x * 32 + threadIdx.x;
    int y = blockIdx.y * 32 + threadIdx.y;
#pragma unroll
    for (int j = 0; j < 32; j += 8)
        t[threadIdx.y + j][threadIdx.x] = W[(size_t)(y + j) * Cn + x];
    __syncthreads();
    int ox = blockIdx.y * 32 + threadIdx.x;
    int oy = blockIdx.x * 32 + threadIdx.y;
#pragma unroll
    for (int j = 0; j < 32; j += 8) {
        float v = t[threadIdx.x][threadIdx.y + j];
        __nv_bfloat16 h, l;
        split2(v, h, l);
        th[(size_t)(oy + j) * R + ox] = h;
        tl[(size_t)(oy + j) * R + ox] = l;
    }
}

// ---------------- bf16x3 GEMM: mma.sync + ldmatrix, 3-stage swizzled --------
// Per stage: Ah/Al/Bh/Bl, each 128 rows x 64B, XOR-swizzled 16B chunks.
#define TS2     8192                 // one tensor tile per stage
#define STG2    (4 * TS2)            // 32 KB per stage
#define GEMM_SMEM (3 * STG2)         // 96 KB

__global__ __launch_bounds__(256) void gemm_mma(
    const __nv_bfloat16* __restrict__ Ah, const __nv_bfloat16* __restrict__ Al,
    const __nv_bfloat16* __restrict__ Bh, const __nv_bfloat16* __restrict__ Bl,
    float* __restrict__ Cc, const float* __restrict__ bias, int M, int N)
{
    extern __shared__ __align__(128) char smem[];
    const uint32_t sb = su32(smem);
    const int tid  = threadIdx.x;
    const int wid  = tid >> 5, lane = tid & 31;
    const int gid  = lane >> 2, tig = lane & 3;
    const int wm   = wid & 1, wn = wid >> 1;          // 2 x 4 warp grid
    const int row0 = blockIdx.y * 128, col0 = blockIdx.x * 128;

    float acc[4][4][4];
#pragma unroll
    for (int i = 0; i < 4; ++i)
#pragma unroll
        for (int j = 0; j < 4; ++j)
#pragma unroll
            for (int k = 0; k < 4; ++k) acc[i][j][k] = 0.f;

    // per-lane ldmatrix row/chunk decomposition (swizzle-aware)
    const int rlA = (lane & 7) + ((lane >> 3) & 1) * 8;   // row within m16 tile
    const int kcA = (lane >> 4) & 1;                       // base 16B chunk
    const int swA = (rlA >> 1) & 3;
    const int rlB = (lane & 7) + ((lane >> 4) & 1) * 8;   // row within two n8 tiles
    const int kcB = (lane >> 3) & 1;
    const int swB = (rlB >> 1) & 3;
    const uint32_t aRow = (uint32_t)(wm * 64 + rlA) * 64u;
    const uint32_t bRow = (uint32_t)(wn * 32 + rlB) * 64u;

    // cp.async mapping: per tensor 512 16B-chunks; thread does chunk tid, tid+256
    const int r0c = tid >> 2, j0c = tid & 3;
    const int r1c = (tid + 256) >> 2, j1c = tid & 3;

    auto issue = [&](int c) {
        const int k0 = c * BK;
        const uint32_t stg = sb + (uint32_t)(c % 3) * STG2;
#pragma unroll
        for (int rep = 0; rep < 2; ++rep) {
            const int row = rep ? r1c : r0c;
            const int j   = rep ? j1c : j0c;
            const uint32_t d = stg + (uint32_t)row * 64u
                             + (uint32_t)((j ^ ((row >> 1) & 3)) * 16);
            const int grA = row0 + row;
            const bool okA = grA < M;
            const size_t aoff = (size_t)(okA ? grA : 0) * KDIM + k0 + j * 8;
            cp16(d,           Ah + aoff, okA);
            cp16(d + TS2,     Al + aoff, okA);
            const size_t boff = (size_t)(col0 + row) * KDIM + k0 + j * 8;
            cp16(d + 2 * TS2, Bh + boff, true);
            cp16(d + 3 * TS2, Bl + boff, true);
        }
        asm volatile("cp.async.commit_group;" ::: "memory");
    };

    issue(0);
    issue(1);

    for (int c = 0; c < NSTG; ++c) {
        asm volatile("cp.async.wait_group 1;" ::: "memory");
        __syncthreads();
        if (c + 2 < NSTG) issue(c + 2);

        const uint32_t stg = sb + (uint32_t)(c % 3) * STG2;

#pragma unroll
        for (int kk = 0; kk < 2; ++kk) {
            const uint32_t aCh = (uint32_t)(((kcA + 2 * kk) ^ swA) * 16);
            const uint32_t bCh = (uint32_t)(((kcB + 2 * kk) ^ swB) * 16);
            uint32_t ah[4][4], al[4][4], bh[4][2], bl[4][2];
#pragma unroll
            for (int mt = 0; mt < 4; ++mt) {
                const uint32_t aAd = stg + aRow + mt * (16 * 64) + aCh;
                ldsm4(ah[mt][0], ah[mt][1], ah[mt][2], ah[mt][3], aAd);
                ldsm4(al[mt][0], al[mt][1], al[mt][2], al[mt][3], aAd + TS2);
            }
#pragma unroll
            for (int pr = 0; pr < 2; ++pr) {      // covers n-tiles 2pr, 2pr+1
                const uint32_t bAd = stg + bRow + pr * (16 * 64) + bCh;
                ldsm4(bh[2 * pr][0], bh[2 * pr][1], bh[2 * pr + 1][0], bh[2 * pr + 1][1],
                      bAd + 2 * TS2);
                ldsm4(bl[2 * pr][0], bl[2 * pr][1], bl[2 * pr + 1][0], bl[2 * pr + 1][1],
                      bAd + 3 * TS2);
            }
#pragma unroll
            for (int mt = 0; mt < 4; ++mt)
#pragma unroll
                for (int nt = 0; nt < 4; ++nt) mma16816(acc[mt][nt], ah[mt], bh[nt]);
#pragma unroll
            for (int mt = 0; mt < 4; ++mt)
#pragma unroll
                for (int nt = 0; nt < 4; ++nt) mma16816(acc[mt][nt], ah[mt], bl[nt]);
#pragma unroll
            for (int mt = 0; mt < 4; ++mt)
#pragma unroll
                for (int nt = 0; nt < 4; ++nt) mma16816(acc[mt][nt], al[mt], bh[nt]);
        }
    }

    // epilogue
#pragma unroll
    for (int mt = 0; mt < 4; ++mt) {
        const int gr = row0 + wm * 64 + mt * 16 + gid;
#pragma unroll
        for (int nt = 0; nt < 4; ++nt) {
            const int gc = col0 + wn * 32 + nt * 8 + tig * 2;
            float b0 = 0.f, b1 = 0.f;
            if (bias) { b0 = __ldg(bias + gc); b1 = __ldg(bias + gc + 1); }
            if (gr < M) {
                float2 v0 = make_float2(acc[mt][nt][0] + b0, acc[mt][nt][1] + b1);
                *(float2*)(Cc + (size_t)gr * N + gc) = v0;
            }
            if (gr + 8 < M) {
                float2 v1 = make_float2(acc[mt][nt][2] + b0, acc[mt][nt][3] + b1);
                *(float2*)(Cc + (size_t)(gr + 8) * N + gc) = v1;
            }
        }
    }
}

// ============================================================================
// Attention phase 1: column scores. Block=(w, head, b), 128 threads.
// ============================================================================
#define QROWS 64
#define SST   68

__global__ __launch_bounds__(128) void k_colscore(
    const float* __restrict__ qkv, float* __restrict__ sc)
{
    __shared__ float Qs[QROWS * SST];
    __shared__ float Ks[QROWS * SST];
    const int w = blockIdx.x, head = blockIdx.y, b = blockIdx.z;
    const int tid = threadIdx.x;
    const float* base = qkv + (size_t)b * NTOK * C3;
    const int qoff = head * HD;

    for (int idx = tid; idx < QROWS * 16; idx += 128) {
        const int r = idx >> 4, c = idx & 15;
        float4 v = make_float4(0.f, 0.f, 0.f, 0.f);
        if (r < 56) {
            const int n = 1 + r * W_ + w;
            v = *(const float4*)(base + (size_t)n * C3 + qoff + c * 4);
        }
        *(float4*)&Qs[r * SST + c * 4] = v;
    }
    for (int idx = tid; idx < QROWS * 16; idx += 128) {
        const int r = idx >> 4, c = idx & 15;
        float4 v = make_float4(0.f, 0.f, 0.f, 0.f);
        if (r < 57) {
            const int n = (r == 0) ? 0 : (1 + (r - 1) * W_ + w);
            v = *(const float4*)(base + (size_t)n * C3 + C_ + qoff + c * 4);
        }
        *(float4*)&Ks[r * SST + c * 4] = v;
    }
    __syncthreads();

    const int ty = tid >> 3, tx = tid & 7;
    float acc[4][8];
#pragma unroll
    for (int i = 0; i < 4; ++i)
#pragma unroll
        for (int j = 0; j < 8; ++j) acc[i][j] = 0.f;

#pragma unroll 4
    for (int d = 0; d < HD; d += 4) {
        float4 a4[4], b4[8];
#pragma unroll
        for (int i = 0; i < 4; ++i) a4[i] = *(float4*)&Qs[(ty + 16 * i) * SST + d];
#pragma unroll
        for (int j = 0; j < 8; ++j) b4[j] = *(float4*)&Ks[(tx + 8 * j) * SST + d];
#pragma unroll
        for (int i = 0; i < 4; ++i)
#pragma unroll
            for (int j = 0; j < 8; ++j) {
                acc[i][j] += a4[i].x * b4[j].x;
                acc[i][j] += a4[i].y * b4[j].y;
                acc[i][j] += a4[i].z * b4[j].z;
                acc[i][j] += a4[i].w * b4[j].w;
            }
    }

    float* out = sc + ((((size_t)b * NH_ + head) * H_) * W_ + w) * 64;
#pragma unroll
    for (int i = 0; i < 4; ++i) {
        const int hq = ty + 16 * i;
        if (hq >= 56) continue;
#pragma unroll
        for (int j = 0; j < 8; ++j) {
            const int jk = tx + 8 * j;
            if (jk < 57)
                out[(size_t)hq * (W_ * 64) + jk] = acc[i][j] * 0.125f;
        }
    }
}

// ============================================================================
// Attention phase 2: row scores + full softmax + row aggregation.
// ============================================================================
#define PST 132
#define K2_SMEM ((2 * QROWS * SST + QROWS * PST) * 4)

__global__ __launch_bounds__(128) void k_rowfused(
    const float* __restrict__ qkv, float* __restrict__ sc,
    float* __restrict__ attp)
{
    extern __shared__ float sm[];
    float* Qs = sm;
    float* Kr = sm + QROWS * SST;
    float* P  = sm + 2 * QROWS * SST;
    const int h = blockIdx.x, head = blockIdx.y, b = blockIdx.z;
    const int tid = threadIdx.x;
    const float* base = qkv + (size_t)b * NTOK * C3;
    const int qoff = head * HD;
    const int nrow0 = 1 + h * W_;

    for (int idx = tid; idx < QROWS * 16; idx += 128) {
        const int r = idx >> 4, c = idx & 15;
        float4 qv = make_float4(0.f, 0.f, 0.f, 0.f);
        float4 kv = qv;
        if (r < 56) {
            const float* tok = base + (size_t)(nrow0 + r) * C3;
            qv = *(const float4*)(tok + qoff + c * 4);
            kv = *(const float4*)(tok + C_ + qoff + c * 4);
        }
        *(float4*)&Qs[r * SST + c * 4] = qv;
        *(float4*)&Kr[r * SST + c * 4] = kv;
    }
    __syncthreads();

    const int ty = tid >> 3, tx = tid & 7;
    {
        float acc[4][8];
#pragma unroll
        for (int i = 0; i < 4; ++i)
#pragma unroll
            for (int j = 0; j < 8; ++j) acc[i][j] = 0.f;
#pragma unroll 4
        for (int d = 0; d < HD; d += 4) {
            float4 a4[4], b4[8];
#pragma unroll
            for (int i = 0; i < 4; ++i) a4[i] = *(float4*)&Qs[(ty + 16 * i) * SST + d];
#pragma unroll
            for (int j = 0; j < 8; ++j) b4[j] = *(float4*)&Kr[(tx + 8 * j) * SST + d];
#pragma unroll
            for (int i = 0; i < 4; ++i)
#pragma unroll
                for (int j = 0; j < 8; ++j) {
                    acc[i][j] += a4[i].x * b4[j].x;
                    acc[i][j] += a4[i].y * b4[j].y;
                    acc[i][j] += a4[i].z * b4[j].z;
                    acc[i][j] += a4[i].w * b4[j].w;
                }
        }
#pragma unroll
        for (int i = 0; i < 4; ++i) {
            const int q = ty + 16 * i;
#pragma unroll
            for (int j = 0; j < 8; ++j) {
                const int k = tx + 8 * j;
                P[q * PST + 60 + k] = (k == q) ? -1e30f : acc[i][j] * 0.125f;
            }
        }
    }
    __syncthreads();

    for (int idx = tid; idx < 56 * 16; idx += 128) {
        const int r = idx >> 4, c = idx & 15;
        *(float4*)&Qs[r * SST + c * 4] =
            *(const float4*)(base + (size_t)(nrow0 + r) * C3 + 2 * C_ + qoff + c * 4);
    }
    {
        const float* scb = sc + ((((size_t)b * NH_ + head) * H_ + h) * W_) * 64;
        for (int idx = tid; idx < 56 * 57; idx += 128) {
            const int q = idx / 57, j = idx % 57;
            P[q * PST + j] = scb[(size_t)q * 64 + j];
        }
    }
    __syncthreads();

    if (tid < 56) {
        float* row = P + tid * PST;
        float m = -1e30f;
#pragma unroll 4
        for (int j = 0; j < 57; ++j) m = fmaxf(m, row[j]);
#pragma unroll 4
        for (int j = 60; j < 116; ++j) m = fmaxf(m, row[j]);
        float s = 0.f;
#pragma unroll 4
        for (int j = 0; j < 57; ++j) { float e = __expf(row[j] - m); row[j] = e; s += e; }
#pragma unroll 4
        for (int j = 60; j < 116; ++j) { float e = __expf(row[j] - m); row[j] = e; s += e; }
        const float inv = 1.f / s;
#pragma unroll 4
        for (int j = 0; j < 57; ++j) row[j] *= inv;
#pragma unroll 4
        for (int j = 60; j < 116; ++j) row[j] *= inv;
    }
    __syncthreads();

    {
        float* scb = sc + ((((size_t)b * NH_ + head) * H_ + h) * W_) * 64;
        for (int idx = tid; idx < 56 * 57; idx += 128) {
            const int q = idx / 57, j = idx % 57;
            scb[(size_t)q * 64 + j] = P[q * PST + j];
        }
    }

    {
        float acc[4][8];
#pragma unroll
        for (int i = 0; i < 4; ++i)
#pragma unroll
            for (int j = 0; j < 8; ++j) acc[i][j] = 0.f;
        for (int k = 0; k < 56; ++k) {
            float af[4], bf[8];
#pragma unroll
            for (int i = 0; i < 4; ++i) af[i] = P[(ty + 16 * i) * PST + 60 + k];
#pragma unroll
            for (int j = 0; j < 8; ++j) bf[j] = Qs[k * SST + tx + 8 * j];
#pragma unroll
            for (int i = 0; i < 4; ++i)
#pragma unroll
                for (int j = 0; j < 8; ++j) acc[i][j] += af[i] * bf[j];
        }
#pragma unroll
        for (int i = 0; i < 4; ++i) {
            const int q = ty + 16 * i;
            if (q >= 56) continue;
            float* op = attp + ((size_t)b * NTOK + nrow0 + q) * C_ + qoff;
#pragma unroll
            for (int j = 0; j < 8; ++j) op[tx + 8 * j] = acc[i][j];
        }
    }
}

// ============================================================================
// Attention phase 3: column aggregation + final hi/lo emit.
// ============================================================================
__global__ __launch_bounds__(128) void k_colagg(
    const float* __restrict__ qkv, const float* __restrict__ sc,
    const float* __restrict__ attp,
    __nv_bfloat16* __restrict__ outh, __nv_bfloat16* __restrict__ outl)
{
    __shared__ float Vc[57 * SST];
    __shared__ float Pc[64 * 60];
    const int w = blockIdx.x, head = blockIdx.y, b = blockIdx.z;
    const int tid = threadIdx.x;
    const float* base = qkv + (size_t)b * NTOK * C3;
    const int qoff = head * HD;

    for (int idx = tid; idx < 57 * 16; idx += 128) {
        const int r = idx >> 4, c = idx & 15;
        const int n = (r == 0) ? 0 : (1 + (r - 1) * W_ + w);
        *(float4*)&Vc[r * SST + c * 4] =
            *(const float4*)(base + (size_t)n * C3 + 2 * C_ + qoff + c * 4);
    }
    {
        const float* scb = sc + (((size_t)b * NH_ + head) * H_) * (W_ * 64) + (size_t)w * 64;
        for (int idx = tid; idx < 56 * 57; idx += 128) {
            const int q = idx / 57, j = idx % 57;
            Pc[q * 60 + j] = scb[(size_t)q * (W_ * 64) + j];
        }
    }
    __syncthreads();

    const int ty = tid >> 3, tx = tid & 7;
    float acc[4][8];
#pragma unroll
    for (int i = 0; i < 4; ++i)
#pragma unroll
        for (int j = 0; j < 8; ++j) acc[i][j] = 0.f;
    for (int k = 0; k < 57; ++k) {
        float af[4], bf[8];
#pragma unroll
        for (int i = 0; i < 4; ++i) af[i] = Pc[(ty + 16 * i) * 60 + k];
#pragma unroll
        for (int j = 0; j < 8; ++j) bf[j] = Vc[k * SST + tx + 8 * j];
#pragma unroll
        for (int i = 0; i < 4; ++i)
#pragma unroll
            for (int j = 0; j < 8; ++j) acc[i][j] += af[i] * bf[j];
    }
#pragma unroll
    for (int i = 0; i < 4; ++i) {
        const int hq = ty + 16 * i;
        if (hq >= 56) continue;
        const size_t off = ((size_t)b * NTOK + 1 + hq * W_ + w) * C_ + qoff;
#pragma unroll
        for (int j = 0; j < 8; ++j) {
            const int d = tx + 8 * j;
            float v = acc[i][j] + attp[off + d];
            __nv_bfloat16 hh, ll;
            split2(v, hh, ll);
            outh[off + d] = hh;
            outl[off + d] = ll;
        }
    }
}

// ---------------- CLS-token attention ---------------------------------------
__global__ __launch_bounds__(256) void attn_cls(
    const float* __restrict__ qkv,
    __nv_bfloat16* __restrict__ outh, __nv_bfloat16* __restrict__ outl)
{
    const int b  = blockIdx.x / NH_;
    const int nh = blockIdx.x % NH_;
    const int tid = threadIdx.x;

    __shared__ float qs[HD];
    __shared__ float scs[NTOK];
    __shared__ float red[256];
    __shared__ float part[4][HD];

    const float* base = qkv + (size_t)b * NTOK * C3;
    if (tid < HD) qs[tid] = base[nh * HD + tid];
    __syncthreads();

    for (int n = tid; n < NTOK; n += 256) {
        const float* kp = base + (size_t)n * C3 + C_ + nh * HD;
        float s = 0.f;
#pragma unroll
        for (int d = 0; d < HD; ++d) s += qs[d] * kp[d];
        scs[n] = s * 0.125f;
    }
    __syncthreads();

    float m = -1e30f;
    for (int n = tid; n < NTOK; n += 256) m = fmaxf(m, scs[n]);
    red[tid] = m;
    __syncthreads();
    for (int st = 128; st; st >>= 1) {
        if (tid < st) red[tid] = fmaxf(red[tid], red[tid + st]);
        __syncthreads();
    }
    m = red[0];
    __syncthreads();

    float s = 0.f;
    for (int n = tid; n < NTOK; n += 256) {
        float e = __expf(scs[n] - m);
        scs[n] = e;
        s += e;
    }
    red[tid] = s;
    __syncthreads();
    for (int st = 128; st; st >>= 1) {
        if (tid < st) red[tid] += red[tid + st];
        __syncthreads();
    }
    const float inv = 1.f / red[0];
    __syncthreads();

    const int d = tid & 63, chunk = tid >> 6;
    float acc = 0.f;
    for (int n = chunk; n < NTOK; n += 4) {
        const float* vp = base + (size_t)n * C3 + 2 * C_ + nh * HD;
        acc += scs[n] * vp[d];
    }
    part[chunk][d] = acc;
    __syncthreads();
    if (chunk == 0) {
        float r = (part[0][d] + part[1][d] + part[2][d] + part[3][d]) * inv;
        __nv_bfloat16 hh, ll;
        split2(r, hh, ll);
        const size_t ooff = (size_t)b * NTOK * C_ + nh * HD + d;
        outh[ooff] = hh;
        outl[ooff] = ll;
    }
}

// ---------------------------------------------------------------------------
extern "C" void kernel_launch(void* const* d_in, const int* in_sizes, int n_in,
                              void* d_out, int out_size)
{
    const float* x     = (const float*)d_in[0];
    const float* Wqkv  = (const float*)d_in[1];
    const float* Wproj = (const float*)d_in[2];
    const float* bproj = (const float*)d_in[3];
    float* out = (float*)d_out;

    float *qkv, *att, *sc;
    __nv_bfloat16 *xh, *xl, *ath, *atl, *wqh, *wql, *wph, *wpl;
    cudaGetSymbolAddress((void**)&qkv, g_qkv);
    cudaGetSymbolAddress((void**)&att, g_att);
    cudaGetSymbolAddress((void**)&sc,  g_sc);
    cudaGetSymbolAddress((void**)&xh,  g_xh);
    cudaGetSymbolAddress((void**)&xl,  g_xl);
    cudaGetSymbolAddress((void**)&ath, g_ath);
    cudaGetSymbolAddress((void**)&atl, g_atl);
    cudaGetSymbolAddress((void**)&wqh, g_wqh);
    cudaGetSymbolAddress((void**)&wql, g_wql);
    cudaGetSymbolAddress((void**)&wph, g_wph);
    cudaGetSymbolAddress((void**)&wpl, g_wpl);

    cudaFuncSetAttribute(gemm_mma,
                         cudaFuncAttributeMaxDynamicSharedMemorySize, GEMM_SMEM);
    cudaFuncSetAttribute(k_rowfused,
                         cudaFuncAttributeMaxDynamicSharedMemorySize, K2_SMEM);

    // 0) pre-passes
    {
        int n4 = MTOT * C_ / 4;
        k_split<<<(n4 + 255) / 256, 256>>>(x, xh, xl, n4);
        k_tsplit<<<dim3(C3 / 32, C_ / 32), dim3(32, 8)>>>(Wqkv,  wqh, wql, C_, C3);
        k_tsplit<<<dim3(C_ / 32, C_ / 32), dim3(32, 8)>>>(Wproj, wph, wpl, C_, C_);
    }
    // 1) QKV projection (HMMA bf16x3, 3-stage swizzled pipeline)
    gemm_mma<<<dim3(C3 / 128, (MTOT + 127) / 128), 256, GEMM_SMEM>>>(
        xh, xl, wqh, wql, qkv, nullptr, MTOT, C3);
    // 2) attention phases
    {
        dim3 ag(W_, NH_, B_);
        k_colscore<<<ag, 128>>>(qkv, sc);
        dim3 rg(H_, NH_, B_);
        k_rowfused<<<rg, 128, K2_SMEM>>>(qkv, sc, att);
        attn_cls<<<B_ * NH_, 256>>>(qkv, ath, atl);
        k_colagg<<<ag, 128>>>(qkv, sc, att, ath, atl);
    }
    // 3) output projection + bias (HMMA bf16x3, 3-stage swizzled pipeline)
    gemm_mma<<<dim3(C_ / 128, (MTOT + 127) / 128), 256, GEMM_SMEM>>>(
        ath, atl, wph, wpl, out, bproj, MTOT, C_);
}